// round 13
// baseline (speedup 1.0000x reference)
#include <cuda_runtime.h>
#include <cuda_bf16.h>
#include <math.h>
#include <cstdint>

#define NN    50000
#define NE    800000
#define NE2   850000           // NE + NN self loops
#define HC    128
#define NBLK  196              // ceil(NN/256)

// ---------------- scratch (device globals) ----------------------------------
__device__ float  g_wsum[NN];
__device__ float  g_loopw[NN];
__device__ int    g_degc[NN];
__device__ int    g_rowp[NN + 1];
__device__ int    g_fill[NN];
__device__ int    g_blksum[256];
__device__ int    g_blkoff[256];
__device__ int    g_csrc[NE2];
__device__ float  g_cw[NE2];
__device__ float4 g_xl[NN * 32];
__device__ float4 g_xr[NN * 32];
__device__ float4 g_agg[NN * 32];
__device__ float4 g_h1[NN * 32];
__device__ float  g_bnsum[HC];
__device__ float  g_bnsq[HC];
__device__ float4 g_bnscale[32];
__device__ float4 g_bnshift[32];
// W^T bf16 images: [layer][half l/r][hi=0,lo=1][n*128+k]
__device__ __nv_bfloat16 g_Wbf[2][2][2][16384];

// ---------------- HMMA helpers ----------------------------------------------
__device__ __forceinline__ uint32_t smem_u32(const void* p) {
    uint32_t a;
    asm("{ .reg .u64 t; cvta.to.shared.u64 t, %1; cvt.u32.u64 %0, t; }"
        : "=r"(a) : "l"(p));
    return a;
}
#define LDSM_X4(r0, r1, r2, r3, addr) \
    asm volatile("ldmatrix.sync.aligned.m8n8.x4.shared.b16 {%0,%1,%2,%3}, [%4];" \
        : "=r"(r0), "=r"(r1), "=r"(r2), "=r"(r3) : "r"(addr))
#define MMA_BF16(d, a, b0, b1) \
    asm volatile("mma.sync.aligned.m16n8k16.row.col.f32.bf16.bf16.f32 " \
        "{%0,%1,%2,%3}, {%4,%5,%6,%7}, {%8,%9}, {%0,%1,%2,%3};" \
        : "+f"((d)[0]), "+f"((d)[1]), "+f"((d)[2]), "+f"((d)[3]) \
        : "r"((a)[0]), "r"((a)[1]), "r"((a)[2]), "r"((a)[3]), "r"(b0), "r"(b1))

__device__ __forceinline__ uint32_t pack2(__nv_bfloat16 a, __nv_bfloat16 b) {
    return (uint32_t)__bfloat16_as_ushort(a) |
           ((uint32_t)__bfloat16_as_ushort(b) << 16);
}

// ---------------- init ------------------------------------------------------
__global__ void __launch_bounds__(256) k_zero_pre() {
    int i = blockIdx.x * 256 + threadIdx.x;
    if (i < NN) { g_wsum[i] = 0.f; g_degc[i] = 1; }
    if (i < HC) { g_bnsum[i] = 0.f; g_bnsq[i] = 0.f; }
}

// edge_index is int32 (JAX default x64-disabled)
__global__ void __launch_bounds__(256) k_selfloop(const int* __restrict__ ei,
                                                  const float* __restrict__ ew) {
    int e = blockIdx.x * 256 + threadIdx.x;
    if (e >= NE) return;
    int d = ei[NE + e];
    atomicAdd(&g_wsum[d], ew[e]);
    atomicAdd(&g_degc[d], 1);
}

__global__ void __launch_bounds__(256) k_loopw() {
    int i = blockIdx.x * 256 + threadIdx.x;
    if (i < NN) {
        float deg = (float)(g_degc[i] - 1);
        g_loopw[i] = g_wsum[i] / fmaxf(deg, 1.0f);
    }
}

// ---------------- exclusive scan of g_degc -> g_rowp ------------------------
__global__ void __launch_bounds__(256) k_scan1() {
    __shared__ int sm[256];
    int t = threadIdx.x;
    int i = blockIdx.x * 256 + t;
    int v = (i < NN) ? g_degc[i] : 0;
    sm[t] = v;
    __syncthreads();
#pragma unroll
    for (int off = 1; off < 256; off <<= 1) {
        int x = (t >= off) ? sm[t - off] : 0;
        __syncthreads();
        sm[t] += x;
        __syncthreads();
    }
    if (i < NN) g_rowp[i] = sm[t] - v;
    if (t == 255) g_blksum[blockIdx.x] = sm[t];
}

__global__ void __launch_bounds__(256) k_scan2() {
    __shared__ int sm[256];
    int t = threadIdx.x;
    int v = (t < NBLK) ? g_blksum[t] : 0;
    sm[t] = v;
    __syncthreads();
#pragma unroll
    for (int off = 1; off < 256; off <<= 1) {
        int x = (t >= off) ? sm[t - off] : 0;
        __syncthreads();
        sm[t] += x;
        __syncthreads();
    }
    g_blkoff[t] = sm[t] - v;
}

__global__ void __launch_bounds__(256) k_scan3() {
    int i = blockIdx.x * 256 + threadIdx.x;
    if (i < NN) {
        int r = g_rowp[i] + g_blkoff[blockIdx.x];
        g_rowp[i] = r;
        g_fill[i] = r;
    }
    if (i == 0) g_rowp[NN] = NE2;
}

__global__ void __launch_bounds__(256) k_fill(const int* __restrict__ ei,
                                              const float* __restrict__ ew) {
    int e = blockIdx.x * 256 + threadIdx.x;
    if (e >= NE2) return;
    if (e < NE) {
        int s = ei[e], d = ei[NE + e];
        int pos = atomicAdd(&g_fill[d], 1);
        g_csrc[pos] = s;
        g_cw[pos] = ew[e];
    } else {
        int i = e - NE;
        int pos = atomicAdd(&g_fill[i], 1);
        g_csrc[pos] = i;
        g_cw[pos] = g_loopw[i];
    }
}

// ---------------- W -> W^T bf16 hi/lo images --------------------------------
__global__ void __launch_bounds__(256) k_conv_w(const float* __restrict__ Wl1,
                                                const float* __restrict__ Wr1,
                                                const float* __restrict__ Wl2,
                                                const float* __restrict__ Wr2) {
    int i = blockIdx.x * 256 + threadIdx.x;      // [0, 65536)
    int layer = i >> 15;
    int half  = (i >> 14) & 1;
    int e = i & 16383;
    int n = e >> 7, k = e & 127;
    const float* W = layer ? (half ? Wr2 : Wl2) : (half ? Wr1 : Wl1);
    float v = W[k * 128 + n];
    __nv_bfloat16 hi = __float2bfloat16_rn(v);
    __nv_bfloat16 lo = __float2bfloat16_rn(v - __bfloat162float(hi));
    g_Wbf[layer][half][0][e] = hi;
    g_Wbf[layer][half][1][e] = lo;
}

// ---------------- fused HMMA GEMM: [xl|xr] = A @ [Wl|Wr] + [bl|br] ----------
// 3-term bf16 split: C = Ah@Bh + Al@Bh + Ah@Bl. One CTA per 128-row tile,
// 512 threads, 16 warps, warp tile 32x64 over a 128x256 output tile.
// smem (bf16, pitch 136): Ah|Al (128 rows) then Bh|Bl (256 n-rows).
#define HPITCH 136
#define HA_B   34816                       // one 128-row image
#define HB_B   69632                       // one 256-row image
#define SOFF_AH 0
#define SOFF_AL 34816
#define SOFF_BH 69632
#define SOFF_BL 139264
#define HG_SMEM 208896

__global__ void __launch_bounds__(512, 1) k_hgemm(const float* __restrict__ Aext,
                                                  int asel, int layer,
                                                  const float* __restrict__ bl,
                                                  const float* __restrict__ br,
                                                  int M) {
    extern __shared__ char smc[];
    const float* A = asel ? (const float*)g_h1 : Aext;

    const int tid = threadIdx.x;
    const int rowBase = blockIdx.x * 128;
    const uint32_t sb = smem_u32(smc);

    // ---- stage A: fp32 -> bf16 hi/lo into padded smem (once per tile) ----
    {
        int row = tid >> 2;
        int cb = (tid & 3) * 32;
        int gr = rowBase + row;
        if (gr >= M) gr = M - 1;
        const float4* src = (const float4*)(A + gr * 128 + cb);
        char* ah = smc + SOFF_AH + (row * HPITCH + cb) * 2;
        char* al = smc + SOFF_AL + (row * HPITCH + cb) * 2;
#pragma unroll
        for (int j = 0; j < 8; j++) {
            float4 v = src[j];
            __nv_bfloat16 hx = __float2bfloat16_rn(v.x);
            __nv_bfloat16 hy = __float2bfloat16_rn(v.y);
            __nv_bfloat16 hz = __float2bfloat16_rn(v.z);
            __nv_bfloat16 hw = __float2bfloat16_rn(v.w);
            uint2 h2 = make_uint2(pack2(hx, hy), pack2(hz, hw));
            uint2 l2 = make_uint2(
                pack2(__float2bfloat16_rn(v.x - __bfloat162float(hx)),
                      __float2bfloat16_rn(v.y - __bfloat162float(hy))),
                pack2(__float2bfloat16_rn(v.z - __bfloat162float(hz)),
                      __float2bfloat16_rn(v.w - __bfloat162float(hw))));
            *(uint2*)(ah + j * 8) = h2;
            *(uint2*)(al + j * 8) = l2;
        }
    }
    // ---- stage B: both halves' preconverted W^T bf16 -> padded smem ----
    {
        int n = tid >> 1;                  // 0..255 (half = n>>7)
        int kb = (tid & 1) * 64;
        int hsel = n >> 7, n0 = n & 127;
        const uint4* bh = (const uint4*)&g_Wbf[layer][hsel][0][n0 * 128 + kb];
        const uint4* blo = (const uint4*)&g_Wbf[layer][hsel][1][n0 * 128 + kb];
        char* dh = smc + SOFF_BH + (n * HPITCH + kb) * 2;
        char* dl = smc + SOFF_BL + (n * HPITCH + kb) * 2;
#pragma unroll
        for (int j = 0; j < 8; j++) {
            *(uint4*)(dh + j * 16) = bh[j];
            *(uint4*)(dl + j * 16) = blo[j];
        }
    }
    __syncthreads();

    // ---- compute: 16 warps, warp tile 32x64 over 128x256 ----
    const int lane = tid & 31, wid = tid >> 5;
    const int mrow = (wid & 3) * 32;
    const int ncol = (wid >> 2) * 64;      // 0,64,128,192
    const int q = lane >> 3, r = lane & 7;

    float acc[2][8][4];
#pragma unroll
    for (int a = 0; a < 2; a++)
#pragma unroll
        for (int b = 0; b < 8; b++)
#pragma unroll
            for (int c = 0; c < 4; c++) acc[a][b][c] = 0.f;

    // A ldmatrix lane address pieces (validated in R12)
    const int a_r = (q & 1) * 8 + r;
    const int a_k = (q >> 1) * 8;
    // B x4 lane address pieces: lanes 0-7 (nf,k0), 8-15 (nf,k0+8),
    // 16-23 (nf+1,k0), 24-31 (nf+1,k0+8)
    const int b_r = ((lane >> 4) & 1) * 8 + r;
    const int b_k = ((lane >> 3) & 1) * 8;

#pragma unroll
    for (int ks = 0; ks < 8; ks++) {
        int k0 = ks * 16;
        uint32_t ah[2][4], al[2][4];
#pragma unroll
        for (int mf = 0; mf < 2; mf++) {
            uint32_t off = (uint32_t)((mrow + mf * 16 + a_r) * HPITCH + k0 + a_k) * 2;
            LDSM_X4(ah[mf][0], ah[mf][1], ah[mf][2], ah[mf][3], sb + SOFF_AH + off);
            LDSM_X4(al[mf][0], al[mf][1], al[mf][2], al[mf][3], sb + SOFF_AL + off);
        }
#pragma unroll
        for (int nfp = 0; nfp < 4; nfp++) {
            uint32_t boff = (uint32_t)((ncol + nfp * 16 + b_r) * HPITCH + k0 + b_k) * 2;
            uint32_t bh0, bh1, bh2, bh3, bl0, bl1, bl2, bl3;
            LDSM_X4(bh0, bh1, bh2, bh3, sb + SOFF_BH + boff);
            LDSM_X4(bl0, bl1, bl2, bl3, sb + SOFF_BL + boff);
#pragma unroll
            for (int mf = 0; mf < 2; mf++) {
                MMA_BF16(acc[mf][nfp * 2], ah[mf], bh0, bh1);
                MMA_BF16(acc[mf][nfp * 2], al[mf], bh0, bh1);
                MMA_BF16(acc[mf][nfp * 2], ah[mf], bl0, bl1);
                MMA_BF16(acc[mf][nfp * 2 + 1], ah[mf], bh2, bh3);
                MMA_BF16(acc[mf][nfp * 2 + 1], al[mf], bh2, bh3);
                MMA_BF16(acc[mf][nfp * 2 + 1], ah[mf], bl2, bl3);
            }
        }
    }

    // ---- writeback + bias (col<128 -> g_xl/bl, else g_xr/br) ----
#pragma unroll
    for (int mf = 0; mf < 2; mf++) {
        int row0 = rowBase + mrow + mf * 16 + (lane >> 2);
#pragma unroll
        for (int nf = 0; nf < 8; nf++) {
            int col = ncol + nf * 8 + (lane & 3) * 2;
            int hsel = col >> 7, c0 = col & 127;
            const float* bias = hsel ? br : bl;
            float* gout = hsel ? (float*)g_xr : (float*)g_xl;
            float b0 = bias[c0], b1 = bias[c0 + 1];
            if (row0 < M) {
                float2 o = make_float2(acc[mf][nf][0] + b0, acc[mf][nf][1] + b1);
                *(float2*)(gout + row0 * 128 + c0) = o;
            }
            if (row0 + 8 < M) {
                float2 o = make_float2(acc[mf][nf][2] + b0, acc[mf][nf][3] + b1);
                *(float2*)(gout + (row0 + 8) * 128 + c0) = o;
            }
        }
    }
}

// ---------------- fused GATv2 attention: TWO warps per dst node -------------
// depth-3 prefetch; mode 0: write agg; mode 1: out = (emb+h1+agg+bias2)/3.
__global__ void __launch_bounds__(256) k_gat(const float* __restrict__ We,
                                             const float* __restrict__ att,
                                             int mode,
                                             const float* __restrict__ emb,
                                             const float* __restrict__ bias2,
                                             float* __restrict__ out) {
    __shared__ float4 s_acc[4][32];
    __shared__ float  s_den[4][32];

    int wid  = threadIdx.x >> 5;
    int slot = wid >> 1;
    int half = wid & 1;
    int lane = threadIdx.x & 31;
    int node = blockIdx.x * 4 + slot;
    if (node >= NN) return;

    float4 b  = g_xr[node * 32 + lane];
    float4 e4 = ((const float4*)We)[lane];
    float4 t4 = ((const float4*)att)[lane];

    int beg = g_rowp[node];
    int end = g_rowp[node + 1];

    float4 acc = make_float4(0.f, 0.f, 0.f, 0.f);
    float denom = 0.f;

    int j = beg + half;
    float w0 = 0.f, w1 = 0.f, w2 = 0.f;
    float4 a0, a1, a2;
    if (j < end)     { int s = g_csrc[j];     w0 = g_cw[j];     a0 = g_xl[s * 32 + lane]; }
    if (j + 2 < end) { int s = g_csrc[j + 2]; w1 = g_cw[j + 2]; a1 = g_xl[s * 32 + lane]; }
    if (j + 4 < end) { int s = g_csrc[j + 4]; w2 = g_cw[j + 4]; a2 = g_xl[s * 32 + lane]; }

    for (; j < end; j += 2) {
        float w3 = 0.f; float4 a3;
        if (j + 6 < end) {
            int s3 = g_csrc[j + 6];
            w3 = g_cw[j + 6];
            a3 = g_xl[s3 * 32 + lane];
        }

        float mx = fmaf(w0, e4.x, a0.x + b.x); mx = fmaxf(mx, 0.2f * mx);
        float my = fmaf(w0, e4.y, a0.y + b.y); my = fmaxf(my, 0.2f * my);
        float mz = fmaf(w0, e4.z, a0.z + b.z); mz = fmaxf(mz, 0.2f * mz);
        float mw = fmaf(w0, e4.w, a0.w + b.w); mw = fmaxf(mw, 0.2f * mw);

        float p = mx * t4.x + my * t4.y + mz * t4.z + mw * t4.w;
        p += __shfl_xor_sync(0xffffffffu, p, 4);
        p += __shfl_xor_sync(0xffffffffu, p, 2);
        p += __shfl_xor_sync(0xffffffffu, p, 1);
        // logits tiny (weights scaled 0.05): unshifted exp == shifted softmax
        float e = __expf(p);
        denom += e;
        acc.x = fmaf(e, a0.x, acc.x);
        acc.y = fmaf(e, a0.y, acc.y);
        acc.z = fmaf(e, a0.z, acc.z);
        acc.w = fmaf(e, a0.w, acc.w);

        a0 = a1; w0 = w1;
        a1 = a2; w1 = w2;
        a2 = a3; w2 = w3;
    }

    if (half == 1) {
        s_acc[slot][lane] = acc;
        s_den[slot][lane] = denom;
    }
    __syncthreads();
    if (half == 1) return;

    float4 pa = s_acc[slot][lane];
    acc.x += pa.x; acc.y += pa.y; acc.z += pa.z; acc.w += pa.w;
    denom += s_den[slot][lane];

    float inv = __frcp_rn(denom);
    acc.x *= inv; acc.y *= inv; acc.z *= inv; acc.w *= inv;

    if (mode == 0) {
        g_agg[node * 32 + lane] = acc;
    } else {
        int i = node * 32 + lane;
        float4 e = ((const float4*)emb)[i];
        float4 h = g_h1[i];
        float4 bb = ((const float4*)bias2)[lane];
        float4 o;
        const float third = 1.0f / 3.0f;
        o.x = (e.x + h.x + acc.x + bb.x) * third;
        o.y = (e.y + h.y + acc.y + bb.y) * third;
        o.z = (e.z + h.z + acc.z + bb.z) * third;
        o.w = (e.w + h.w + acc.w + bb.w) * third;
        ((float4*)out)[i] = o;
    }
}

// ---------------- batchnorm -------------------------------------------------
__global__ void __launch_bounds__(256) k_bnstats() {
    int t = threadIdx.x;
    int f4 = t & 31;
    float4 s = make_float4(0.f, 0.f, 0.f, 0.f);
    float4 q = make_float4(0.f, 0.f, 0.f, 0.f);
    for (int r = blockIdx.x * 8 + (t >> 5); r < NN; r += gridDim.x * 8) {
        float4 v = g_agg[r * 32 + f4];
        s.x += v.x; s.y += v.y; s.z += v.z; s.w += v.w;
        q.x += v.x * v.x; q.y += v.y * v.y; q.z += v.z * v.z; q.w += v.w * v.w;
    }
    int j = f4 * 4;
    atomicAdd(&g_bnsum[j + 0], s.x); atomicAdd(&g_bnsum[j + 1], s.y);
    atomicAdd(&g_bnsum[j + 2], s.z); atomicAdd(&g_bnsum[j + 3], s.w);
    atomicAdd(&g_bnsq[j + 0], q.x);  atomicAdd(&g_bnsq[j + 1], q.y);
    atomicAdd(&g_bnsq[j + 2], q.z);  atomicAdd(&g_bnsq[j + 3], q.w);
}

__global__ void __launch_bounds__(128) k_bnfin(const float* __restrict__ gamma,
                                               const float* __restrict__ beta) {
    int j = threadIdx.x;
    float mean = g_bnsum[j] * (1.0f / NN);
    float var  = g_bnsq[j] * (1.0f / NN) - mean * mean;
    float inv  = rsqrtf(var + 1e-5f);
    float sc   = gamma[j] * inv;
    ((float*)g_bnscale)[j] = sc;
    ((float*)g_bnshift)[j] = beta[j] - mean * sc;
}

__global__ void __launch_bounds__(256) k_bnapply() {
    int i = blockIdx.x * 256 + threadIdx.x;
    if (i >= NN * 32) return;
    int f4 = i & 31;
    float4 v  = g_agg[i];
    float4 sc = g_bnscale[f4];
    float4 sh = g_bnshift[f4];
    float x;
    x = fmaf(v.x, sc.x, sh.x); v.x = x > 0.f ? x : expm1f(x);
    x = fmaf(v.y, sc.y, sh.y); v.y = x > 0.f ? x : expm1f(x);
    x = fmaf(v.z, sc.z, sh.z); v.z = x > 0.f ? x : expm1f(x);
    x = fmaf(v.w, sc.w, sh.w); v.w = x > 0.f ? x : expm1f(x);
    g_h1[i] = v;
}

// ---------------- launch ----------------------------------------------------
extern "C" void kernel_launch(void* const* d_in, const int* in_sizes, int n_in,
                              void* d_out, int out_size) {
    const float* emb   = (const float*)d_in[0];
    const int*   ei    = (const int*)d_in[1];      // int32
    const float* ew    = (const float*)d_in[2];
    const float* Wl1   = (const float*)d_in[3];
    const float* bl1   = (const float*)d_in[4];
    const float* Wr1   = (const float*)d_in[5];
    const float* br1   = (const float*)d_in[6];
    const float* We1   = (const float*)d_in[7];
    const float* att1  = (const float*)d_in[8];
    // d_in[9] = bias1 : cancels exactly inside BatchNorm, unused
    const float* gamma1 = (const float*)d_in[10];
    const float* beta1  = (const float*)d_in[11];
    const float* Wl2   = (const float*)d_in[12];
    const float* bl2   = (const float*)d_in[13];
    const float* Wr2   = (const float*)d_in[14];
    const float* br2   = (const float*)d_in[15];
    const float* We2   = (const float*)d_in[16];
    const float* att2  = (const float*)d_in[17];
    const float* bias2 = (const float*)d_in[18];
    float* out = (float*)d_out;

    static int smem_set = 0;
    if (!smem_set) {
        cudaFuncSetAttribute(k_hgemm, cudaFuncAttributeMaxDynamicSharedMemorySize,
                             HG_SMEM);
        smem_set = 1;
    }

    const int NB_N  = NBLK;
    const int NB_E  = (NE + 255) / 256;
    const int NB_E2 = (NE2 + 255) / 256;
    const int NB_G  = (NN + 3) / 4;
    const int NB_F  = (NN * 32 + 255) / 256;
    const int NB_GM = (NN + 127) / 128;

    // ---- preprocessing: self-loop attrs + CSR + W images ----
    k_zero_pre<<<NB_N, 256>>>();
    k_selfloop<<<NB_E, 256>>>(ei, ew);
    k_loopw<<<NB_N, 256>>>();
    k_scan1<<<NBLK, 256>>>();
    k_scan2<<<1, 256>>>();
    k_scan3<<<NBLK, 256>>>();
    k_fill<<<NB_E2, 256>>>(ei, ew);
    k_conv_w<<<256, 256>>>(Wl1, Wr1, Wl2, Wr2);

    // ---- layer 1 ----
    k_hgemm<<<NB_GM, 512, HG_SMEM>>>(emb, 0, 0, bl1, br1, NN);
    k_gat<<<NB_G, 256>>>(We1, att1, 0, emb, bias2, out);
    k_bnstats<<<512, 256>>>();
    k_bnfin<<<1, 128>>>(gamma1, beta1);
    k_bnapply<<<NB_F, 256>>>();

    // ---- layer 2 ----
    k_hgemm<<<NB_GM, 512, HG_SMEM>>>(emb, 1, 1, bl2, br2, NN);
    // fused final: out = (emb + h1 + (agg + bias2)) / 3
    k_gat<<<NB_G, 256>>>(We2, att2, 1, emb, bias2, out);
}

// round 14
// speedup vs baseline: 1.0144x; 1.0144x over previous
#include <cuda_runtime.h>
#include <cuda_bf16.h>
#include <math.h>
#include <cstdint>

#define NN    50000
#define NE    800000
#define NE2   850000           // NE + NN self loops
#define HC    128
#define NBLK  196              // ceil(NN/256)

// ---------------- scratch (device globals) ----------------------------------
__device__ float  g_wsum[NN];
__device__ float  g_loopw[NN];
__device__ int    g_degc[NN];
__device__ int    g_rowp[NN + 1];
__device__ int    g_fill[NN];
__device__ int    g_blksum[256];
__device__ int    g_blkoff[256];
__device__ int    g_csrc[NE2];
__device__ float  g_cw[NE2];
__device__ float4 g_xl[NN * 32];
__device__ float4 g_xr[NN * 32];
__device__ float4 g_agg[NN * 32];
__device__ float4 g_h1[NN * 32];
__device__ float  g_bnsum[HC];
__device__ float  g_bnsq[HC];
__device__ float4 g_bnscale[32];
__device__ float4 g_bnshift[32];
// W^T bf16 images: [layer][half l/r][hi=0,lo=1][n*128+k]
__device__ __nv_bfloat16 g_Wbf[2][2][2][16384];

// ---------------- HMMA helpers ----------------------------------------------
__device__ __forceinline__ uint32_t smem_u32(const void* p) {
    uint32_t a;
    asm("{ .reg .u64 t; cvta.to.shared.u64 t, %1; cvt.u32.u64 %0, t; }"
        : "=r"(a) : "l"(p));
    return a;
}
#define LDSM_X4(r0, r1, r2, r3, addr) \
    asm volatile("ldmatrix.sync.aligned.m8n8.x4.shared.b16 {%0,%1,%2,%3}, [%4];" \
        : "=r"(r0), "=r"(r1), "=r"(r2), "=r"(r3) : "r"(addr))
#define MMA_BF16(d, a, b0, b1) \
    asm volatile("mma.sync.aligned.m16n8k16.row.col.f32.bf16.bf16.f32 " \
        "{%0,%1,%2,%3}, {%4,%5,%6,%7}, {%8,%9}, {%0,%1,%2,%3};" \
        : "+f"((d)[0]), "+f"((d)[1]), "+f"((d)[2]), "+f"((d)[3]) \
        : "r"((a)[0]), "r"((a)[1]), "r"((a)[2]), "r"((a)[3]), "r"(b0), "r"(b1))

__device__ __forceinline__ uint32_t pack2(__nv_bfloat16 a, __nv_bfloat16 b) {
    return (uint32_t)__bfloat16_as_ushort(a) |
           ((uint32_t)__bfloat16_as_ushort(b) << 16);
}

// ---------------- init ------------------------------------------------------
__global__ void __launch_bounds__(256) k_zero_pre() {
    int i = blockIdx.x * 256 + threadIdx.x;
    if (i < NN) { g_wsum[i] = 0.f; g_degc[i] = 1; }
    if (i < HC) { g_bnsum[i] = 0.f; g_bnsq[i] = 0.f; }
}

// edge_index is int32 (JAX default x64-disabled)
__global__ void __launch_bounds__(256) k_selfloop(const int* __restrict__ ei,
                                                  const float* __restrict__ ew) {
    int e = blockIdx.x * 256 + threadIdx.x;
    if (e >= NE) return;
    int d = ei[NE + e];
    atomicAdd(&g_wsum[d], ew[e]);
    atomicAdd(&g_degc[d], 1);
}

__global__ void __launch_bounds__(256) k_loopw() {
    int i = blockIdx.x * 256 + threadIdx.x;
    if (i < NN) {
        float deg = (float)(g_degc[i] - 1);
        g_loopw[i] = g_wsum[i] / fmaxf(deg, 1.0f);
    }
}

// ---------------- exclusive scan of g_degc -> g_rowp ------------------------
__global__ void __launch_bounds__(256) k_scan1() {
    __shared__ int sm[256];
    int t = threadIdx.x;
    int i = blockIdx.x * 256 + t;
    int v = (i < NN) ? g_degc[i] : 0;
    sm[t] = v;
    __syncthreads();
#pragma unroll
    for (int off = 1; off < 256; off <<= 1) {
        int x = (t >= off) ? sm[t - off] : 0;
        __syncthreads();
        sm[t] += x;
        __syncthreads();
    }
    if (i < NN) g_rowp[i] = sm[t] - v;
    if (t == 255) g_blksum[blockIdx.x] = sm[t];
}

__global__ void __launch_bounds__(256) k_scan2() {
    __shared__ int sm[256];
    int t = threadIdx.x;
    int v = (t < NBLK) ? g_blksum[t] : 0;
    sm[t] = v;
    __syncthreads();
#pragma unroll
    for (int off = 1; off < 256; off <<= 1) {
        int x = (t >= off) ? sm[t - off] : 0;
        __syncthreads();
        sm[t] += x;
        __syncthreads();
    }
    g_blkoff[t] = sm[t] - v;
}

__global__ void __launch_bounds__(256) k_scan3() {
    int i = blockIdx.x * 256 + threadIdx.x;
    if (i < NN) {
        int r = g_rowp[i] + g_blkoff[blockIdx.x];
        g_rowp[i] = r;
        g_fill[i] = r;
    }
    if (i == 0) g_rowp[NN] = NE2;
}

__global__ void __launch_bounds__(256) k_fill(const int* __restrict__ ei,
                                              const float* __restrict__ ew) {
    int e = blockIdx.x * 256 + threadIdx.x;
    if (e >= NE2) return;
    if (e < NE) {
        int s = ei[e], d = ei[NE + e];
        int pos = atomicAdd(&g_fill[d], 1);
        g_csrc[pos] = s;
        g_cw[pos] = ew[e];
    } else {
        int i = e - NE;
        int pos = atomicAdd(&g_fill[i], 1);
        g_csrc[pos] = i;
        g_cw[pos] = g_loopw[i];
    }
}

// ---------------- W -> W^T bf16 hi/lo images --------------------------------
__global__ void __launch_bounds__(256) k_conv_w(const float* __restrict__ Wl1,
                                                const float* __restrict__ Wr1,
                                                const float* __restrict__ Wl2,
                                                const float* __restrict__ Wr2) {
    int i = blockIdx.x * 256 + threadIdx.x;      // [0, 65536)
    int layer = i >> 15;
    int half  = (i >> 14) & 1;
    int e = i & 16383;
    int n = e >> 7, k = e & 127;
    const float* W = layer ? (half ? Wr2 : Wl2) : (half ? Wr1 : Wl1);
    float v = W[k * 128 + n];
    __nv_bfloat16 hi = __float2bfloat16_rn(v);
    __nv_bfloat16 lo = __float2bfloat16_rn(v - __bfloat162float(hi));
    g_Wbf[layer][half][0][e] = hi;
    g_Wbf[layer][half][1][e] = lo;
}

// ---------------- HMMA GEMM (R12 structure + x4 B loads) --------------------
// C[M,128] = A[M,128] @ W + bias, 3-term bf16 split: Ah@Bh + Al@Bh + Ah@Bl.
// blockIdx.y: 0 -> g_xl (Wl, bl), 1 -> g_xr (Wr, br). asel: 0 ext A, 1 g_h1.
// smem (bf16, pitch 136): Ah | Al | Bh | Bl, 34816 B each = 139264 B total.
#define HPITCH 136
#define HAS_B  34816
#define HG_SMEM (4 * 34816)

__global__ void __launch_bounds__(256) k_hgemm(const float* __restrict__ Aext,
                                               int asel, int layer,
                                               const float* __restrict__ bl,
                                               const float* __restrict__ br,
                                               int M) {
    extern __shared__ char smc[];
    const float* A    = asel ? (const float*)g_h1 : Aext;
    const int    y    = blockIdx.y;
    const float* bias = y ? br : bl;
    float*       gout = y ? (float*)g_xr : (float*)g_xl;

    const int tid = threadIdx.x;
    const int rowBase = blockIdx.x * 128;
    const uint32_t sb = smem_u32(smc);
    const uint32_t AH = sb, AL = sb + HAS_B, BH = sb + 2 * HAS_B, BL = sb + 3 * HAS_B;

    // ---- stage A: fp32 -> bf16 hi/lo into padded smem ----
    {
        int row = tid >> 1;
        int cb = (tid & 1) * 64;
        int gr = rowBase + row;
        if (gr >= M) gr = M - 1;
        const float4* src = (const float4*)(A + gr * 128 + cb);
        char* ah = smc + (row * HPITCH + cb) * 2;
        char* al = ah + HAS_B;
#pragma unroll
        for (int j = 0; j < 16; j++) {
            float4 v = src[j];
            __nv_bfloat16 hx = __float2bfloat16_rn(v.x);
            __nv_bfloat16 hy = __float2bfloat16_rn(v.y);
            __nv_bfloat16 hz = __float2bfloat16_rn(v.z);
            __nv_bfloat16 hw = __float2bfloat16_rn(v.w);
            uint2 h2 = make_uint2(pack2(hx, hy), pack2(hz, hw));
            uint2 l2 = make_uint2(
                pack2(__float2bfloat16_rn(v.x - __bfloat162float(hx)),
                      __float2bfloat16_rn(v.y - __bfloat162float(hy))),
                pack2(__float2bfloat16_rn(v.z - __bfloat162float(hz)),
                      __float2bfloat16_rn(v.w - __bfloat162float(hw))));
            *(uint2*)(ah + j * 8) = h2;
            *(uint2*)(al + j * 8) = l2;
        }
    }
    // ---- stage B: preconverted W^T bf16 -> padded smem ----
    {
        int n = tid >> 1;
        int kb = (tid & 1) * 64;
        const uint4* bh = (const uint4*)&g_Wbf[layer][y][0][n * 128 + kb];
        const uint4* blo = (const uint4*)&g_Wbf[layer][y][1][n * 128 + kb];
        char* dh = smc + 2 * HAS_B + (n * HPITCH + kb) * 2;
        char* dl = dh + HAS_B;
#pragma unroll
        for (int j = 0; j < 8; j++) {
            *(uint4*)(dh + j * 16) = bh[j];
            *(uint4*)(dl + j * 16) = blo[j];
        }
    }
    __syncthreads();

    // ---- compute: 8 warps, warp tile 32x64 ----
    const int lane = tid & 31, wid = tid >> 5;
    const int mrow = (wid & 3) * 32;
    const int ncol = (wid >> 2) * 64;
    const int q = lane >> 3, r = lane & 7;

    float acc[2][8][4];
#pragma unroll
    for (int a = 0; a < 2; a++)
#pragma unroll
        for (int b = 0; b < 8; b++)
#pragma unroll
            for (int c = 0; c < 4; c++) acc[a][b][c] = 0.f;

    // A ldmatrix lane address pieces (validated R12)
    const int a_r = (q & 1) * 8 + r;
    const int a_k = (q >> 1) * 8;
    // B x4 lane address pieces (validated R13): lanes 0-7 (nf,k0),
    // 8-15 (nf,k0+8), 16-23 (nf+1,k0), 24-31 (nf+1,k0+8)
    const int b_r = ((lane >> 4) & 1) * 8 + r;
    const int b_k = ((lane >> 3) & 1) * 8;

#pragma unroll
    for (int ks = 0; ks < 8; ks++) {
        int k0 = ks * 16;
        uint32_t ah[2][4], al[2][4];
#pragma unroll
        for (int mf = 0; mf < 2; mf++) {
            uint32_t off = (uint32_t)((mrow + mf * 16 + a_r) * HPITCH + k0 + a_k) * 2;
            LDSM_X4(ah[mf][0], ah[mf][1], ah[mf][2], ah[mf][3], AH + off);
            LDSM_X4(al[mf][0], al[mf][1], al[mf][2], al[mf][3], AL + off);
        }
#pragma unroll
        for (int nfp = 0; nfp < 4; nfp++) {
            uint32_t boff = (uint32_t)((ncol + nfp * 16 + b_r) * HPITCH + k0 + b_k) * 2;
            uint32_t bh0, bh1, bh2, bh3, bl0, bl1, bl2, bl3;
            LDSM_X4(bh0, bh1, bh2, bh3, BH + boff);
            LDSM_X4(bl0, bl1, bl2, bl3, BL + boff);
#pragma unroll
            for (int mf = 0; mf < 2; mf++) {
                MMA_BF16(acc[mf][nfp * 2], ah[mf], bh0, bh1);
                MMA_BF16(acc[mf][nfp * 2], al[mf], bh0, bh1);
                MMA_BF16(acc[mf][nfp * 2], ah[mf], bl0, bl1);
                MMA_BF16(acc[mf][nfp * 2 + 1], ah[mf], bh2, bh3);
                MMA_BF16(acc[mf][nfp * 2 + 1], al[mf], bh2, bh3);
                MMA_BF16(acc[mf][nfp * 2 + 1], ah[mf], bl2, bl3);
            }
        }
    }

    // ---- writeback + bias ----
#pragma unroll
    for (int mf = 0; mf < 2; mf++) {
        int row0 = rowBase + mrow + mf * 16 + (lane >> 2);
#pragma unroll
        for (int nf = 0; nf < 8; nf++) {
            int col = ncol + nf * 8 + (lane & 3) * 2;
            float b0 = bias[col], b1 = bias[col + 1];
            if (row0 < M) {
                float2 o = make_float2(acc[mf][nf][0] + b0, acc[mf][nf][1] + b1);
                *(float2*)(gout + row0 * 128 + col) = o;
            }
            if (row0 + 8 < M) {
                float2 o = make_float2(acc[mf][nf][2] + b0, acc[mf][nf][3] + b1);
                *(float2*)(gout + (row0 + 8) * 128 + col) = o;
            }
        }
    }
}

// ---------------- fused GATv2 attention: TWO warps per dst node -------------
// depth-3 prefetch; mode 0: write agg; mode 1: out = (emb+h1+agg+bias2)/3.
__global__ void __launch_bounds__(256) k_gat(const float* __restrict__ We,
                                             const float* __restrict__ att,
                                             int mode,
                                             const float* __restrict__ emb,
                                             const float* __restrict__ bias2,
                                             float* __restrict__ out) {
    __shared__ float4 s_acc[4][32];
    __shared__ float  s_den[4][32];

    int wid  = threadIdx.x >> 5;
    int slot = wid >> 1;
    int half = wid & 1;
    int lane = threadIdx.x & 31;
    int node = blockIdx.x * 4 + slot;
    if (node >= NN) return;

    float4 b  = g_xr[node * 32 + lane];
    float4 e4 = ((const float4*)We)[lane];
    float4 t4 = ((const float4*)att)[lane];

    int beg = g_rowp[node];
    int end = g_rowp[node + 1];

    float4 acc = make_float4(0.f, 0.f, 0.f, 0.f);
    float denom = 0.f;

    int j = beg + half;
    float w0 = 0.f, w1 = 0.f, w2 = 0.f;
    float4 a0, a1, a2;
    if (j < end)     { int s = g_csrc[j];     w0 = g_cw[j];     a0 = g_xl[s * 32 + lane]; }
    if (j + 2 < end) { int s = g_csrc[j + 2]; w1 = g_cw[j + 2]; a1 = g_xl[s * 32 + lane]; }
    if (j + 4 < end) { int s = g_csrc[j + 4]; w2 = g_cw[j + 4]; a2 = g_xl[s * 32 + lane]; }

    for (; j < end; j += 2) {
        float w3 = 0.f; float4 a3;
        if (j + 6 < end) {
            int s3 = g_csrc[j + 6];
            w3 = g_cw[j + 6];
            a3 = g_xl[s3 * 32 + lane];
        }

        float mx = fmaf(w0, e4.x, a0.x + b.x); mx = fmaxf(mx, 0.2f * mx);
        float my = fmaf(w0, e4.y, a0.y + b.y); my = fmaxf(my, 0.2f * my);
        float mz = fmaf(w0, e4.z, a0.z + b.z); mz = fmaxf(mz, 0.2f * mz);
        float mw = fmaf(w0, e4.w, a0.w + b.w); mw = fmaxf(mw, 0.2f * mw);

        float p = mx * t4.x + my * t4.y + mz * t4.z + mw * t4.w;
        p += __shfl_xor_sync(0xffffffffu, p, 4);
        p += __shfl_xor_sync(0xffffffffu, p, 2);
        p += __shfl_xor_sync(0xffffffffu, p, 1);
        // logits tiny (weights scaled 0.05): unshifted exp == shifted softmax
        float e = __expf(p);
        denom += e;
        acc.x = fmaf(e, a0.x, acc.x);
        acc.y = fmaf(e, a0.y, acc.y);
        acc.z = fmaf(e, a0.z, acc.z);
        acc.w = fmaf(e, a0.w, acc.w);

        a0 = a1; w0 = w1;
        a1 = a2; w1 = w2;
        a2 = a3; w2 = w3;
    }

    if (half == 1) {
        s_acc[slot][lane] = acc;
        s_den[slot][lane] = denom;
    }
    __syncthreads();
    if (half == 1) return;

    float4 pa = s_acc[slot][lane];
    acc.x += pa.x; acc.y += pa.y; acc.z += pa.z; acc.w += pa.w;
    denom += s_den[slot][lane];

    float inv = __frcp_rn(denom);
    acc.x *= inv; acc.y *= inv; acc.z *= inv; acc.w *= inv;

    if (mode == 0) {
        g_agg[node * 32 + lane] = acc;
    } else {
        int i = node * 32 + lane;
        float4 e = ((const float4*)emb)[i];
        float4 h = g_h1[i];
        float4 bb = ((const float4*)bias2)[lane];
        float4 o;
        const float third = 1.0f / 3.0f;
        o.x = (e.x + h.x + acc.x + bb.x) * third;
        o.y = (e.y + h.y + acc.y + bb.y) * third;
        o.z = (e.z + h.z + acc.z + bb.z) * third;
        o.w = (e.w + h.w + acc.w + bb.w) * third;
        ((float4*)out)[i] = o;
    }
}

// ---------------- batchnorm -------------------------------------------------
__global__ void __launch_bounds__(256) k_bnstats() {
    int t = threadIdx.x;
    int f4 = t & 31;
    float4 s = make_float4(0.f, 0.f, 0.f, 0.f);
    float4 q = make_float4(0.f, 0.f, 0.f, 0.f);
    for (int r = blockIdx.x * 8 + (t >> 5); r < NN; r += gridDim.x * 8) {
        float4 v = g_agg[r * 32 + f4];
        s.x += v.x; s.y += v.y; s.z += v.z; s.w += v.w;
        q.x += v.x * v.x; q.y += v.y * v.y; q.z += v.z * v.z; q.w += v.w * v.w;
    }
    int j = f4 * 4;
    atomicAdd(&g_bnsum[j + 0], s.x); atomicAdd(&g_bnsum[j + 1], s.y);
    atomicAdd(&g_bnsum[j + 2], s.z); atomicAdd(&g_bnsum[j + 3], s.w);
    atomicAdd(&g_bnsq[j + 0], q.x);  atomicAdd(&g_bnsq[j + 1], q.y);
    atomicAdd(&g_bnsq[j + 2], q.z);  atomicAdd(&g_bnsq[j + 3], q.w);
}

__global__ void __launch_bounds__(128) k_bnfin(const float* __restrict__ gamma,
                                               const float* __restrict__ beta) {
    int j = threadIdx.x;
    float mean = g_bnsum[j] * (1.0f / NN);
    float var  = g_bnsq[j] * (1.0f / NN) - mean * mean;
    float inv  = rsqrtf(var + 1e-5f);
    float sc   = gamma[j] * inv;
    ((float*)g_bnscale)[j] = sc;
    ((float*)g_bnshift)[j] = beta[j] - mean * sc;
}

__global__ void __launch_bounds__(256) k_bnapply() {
    int i = blockIdx.x * 256 + threadIdx.x;
    if (i >= NN * 32) return;
    int f4 = i & 31;
    float4 v  = g_agg[i];
    float4 sc = g_bnscale[f4];
    float4 sh = g_bnshift[f4];
    float x;
    x = fmaf(v.x, sc.x, sh.x); v.x = x > 0.f ? x : expm1f(x);
    x = fmaf(v.y, sc.y, sh.y); v.y = x > 0.f ? x : expm1f(x);
    x = fmaf(v.z, sc.z, sh.z); v.z = x > 0.f ? x : expm1f(x);
    x = fmaf(v.w, sc.w, sh.w); v.w = x > 0.f ? x : expm1f(x);
    g_h1[i] = v;
}

// ---------------- launch ----------------------------------------------------
extern "C" void kernel_launch(void* const* d_in, const int* in_sizes, int n_in,
                              void* d_out, int out_size) {
    const float* emb   = (const float*)d_in[0];
    const int*   ei    = (const int*)d_in[1];      // int32
    const float* ew    = (const float*)d_in[2];
    const float* Wl1   = (const float*)d_in[3];
    const float* bl1   = (const float*)d_in[4];
    const float* Wr1   = (const float*)d_in[5];
    const float* br1   = (const float*)d_in[6];
    const float* We1   = (const float*)d_in[7];
    const float* att1  = (const float*)d_in[8];
    // d_in[9] = bias1 : cancels exactly inside BatchNorm, unused
    const float* gamma1 = (const float*)d_in[10];
    const float* beta1  = (const float*)d_in[11];
    const float* Wl2   = (const float*)d_in[12];
    const float* bl2   = (const float*)d_in[13];
    const float* Wr2   = (const float*)d_in[14];
    const float* br2   = (const float*)d_in[15];
    const float* We2   = (const float*)d_in[16];
    const float* att2  = (const float*)d_in[17];
    const float* bias2 = (const float*)d_in[18];
    float* out = (float*)d_out;

    static int smem_set = 0;
    if (!smem_set) {
        cudaFuncSetAttribute(k_hgemm, cudaFuncAttributeMaxDynamicSharedMemorySize,
                             HG_SMEM);
        smem_set = 1;
    }

    const int NB_N  = NBLK;
    const int NB_E  = (NE + 255) / 256;
    const int NB_E2 = (NE2 + 255) / 256;
    const int NB_G  = (NN + 3) / 4;
    const int NB_F  = (NN * 32 + 255) / 256;
    dim3 gemm_grid((NN + 127) / 128, 2);

    // ---- preprocessing: self-loop attrs + CSR + W images ----
    k_zero_pre<<<NB_N, 256>>>();
    k_selfloop<<<NB_E, 256>>>(ei, ew);
    k_loopw<<<NB_N, 256>>>();
    k_scan1<<<NBLK, 256>>>();
    k_scan2<<<1, 256>>>();
    k_scan3<<<NBLK, 256>>>();
    k_fill<<<NB_E2, 256>>>(ei, ew);
    k_conv_w<<<256, 256>>>(Wl1, Wr1, Wl2, Wr2);

    // ---- layer 1 ----
    k_hgemm<<<gemm_grid, 256, HG_SMEM>>>(emb, 0, 0, bl1, br1, NN);
    k_gat<<<NB_G, 256>>>(We1, att1, 0, emb, bias2, out);
    k_bnstats<<<512, 256>>>();
    k_bnfin<<<1, 128>>>(gamma1, beta1);
    k_bnapply<<<NB_F, 256>>>();

    // ---- layer 2 ----
    k_hgemm<<<gemm_grid, 256, HG_SMEM>>>(emb, 1, 1, bl2, br2, NN);
    // fused final: out = (emb + h1 + (agg + bias2)) / 3
    k_gat<<<NB_G, 256>>>(We2, att2, 1, emb, bias2, out);
}

// round 15
// speedup vs baseline: 1.1203x; 1.1044x over previous
#include <cuda_runtime.h>
#include <cuda_bf16.h>
#include <math.h>
#include <cstdint>

#define NN    50000
#define NE    800000
#define NE2   850000           // NE + NN self loops
#define HC    128
#define NBLK  196              // ceil(NN/256)

// ---------------- scratch (device globals) ----------------------------------
__device__ float  g_wsum[NN];
__device__ float  g_loopw[NN];
__device__ int    g_degc[NN];
__device__ int    g_rowp[NN + 1];
__device__ int    g_fill[NN];
__device__ int    g_blksum[256];
__device__ int    g_blkoff[256];
__device__ int    g_csrc[NE2];
__device__ float  g_cw[NE2];
__device__ float4 g_xl[NN * 32];
__device__ float4 g_xr[NN * 32];
__device__ float4 g_agg[NN * 32];
__device__ float4 g_h1[NN * 32];
__device__ float  g_bnsum[HC];
__device__ float  g_bnsq[HC];
__device__ float4 g_bnscale[32];
__device__ float4 g_bnshift[32];
// W^T bf16 images: [layer][half l/r][hi=0,lo=1][n*128+k]
__device__ __nv_bfloat16 g_Wbf[2][2][2][16384];

// ---------------- HMMA helpers ----------------------------------------------
__device__ __forceinline__ uint32_t smem_u32(const void* p) {
    uint32_t a;
    asm("{ .reg .u64 t; cvta.to.shared.u64 t, %1; cvt.u32.u64 %0, t; }"
        : "=r"(a) : "l"(p));
    return a;
}
#define LDSM_X4(r0, r1, r2, r3, addr) \
    asm volatile("ldmatrix.sync.aligned.m8n8.x4.shared.b16 {%0,%1,%2,%3}, [%4];" \
        : "=r"(r0), "=r"(r1), "=r"(r2), "=r"(r3) : "r"(addr))
#define LDSM_X2(r0, r1, addr) \
    asm volatile("ldmatrix.sync.aligned.m8n8.x2.shared.b16 {%0,%1}, [%2];" \
        : "=r"(r0), "=r"(r1) : "r"(addr))
#define MMA_BF16(d, a, b0, b1) \
    asm volatile("mma.sync.aligned.m16n8k16.row.col.f32.bf16.bf16.f32 " \
        "{%0,%1,%2,%3}, {%4,%5,%6,%7}, {%8,%9}, {%0,%1,%2,%3};" \
        : "+f"((d)[0]), "+f"((d)[1]), "+f"((d)[2]), "+f"((d)[3]) \
        : "r"((a)[0]), "r"((a)[1]), "r"((a)[2]), "r"((a)[3]), "r"(b0), "r"(b1))

__device__ __forceinline__ uint32_t pack2(__nv_bfloat16 a, __nv_bfloat16 b) {
    return (uint32_t)__bfloat16_as_ushort(a) |
           ((uint32_t)__bfloat16_as_ushort(b) << 16);
}

// ---------------- init ------------------------------------------------------
__global__ void __launch_bounds__(256) k_zero_pre() {
    int i = blockIdx.x * 256 + threadIdx.x;
    if (i < NN) { g_wsum[i] = 0.f; g_degc[i] = 1; }
    if (i < HC) { g_bnsum[i] = 0.f; g_bnsq[i] = 0.f; }
}

// edge_index is int32 (JAX default x64-disabled)
__global__ void __launch_bounds__(256) k_selfloop(const int* __restrict__ ei,
                                                  const float* __restrict__ ew) {
    int e = blockIdx.x * 256 + threadIdx.x;
    if (e >= NE) return;
    int d = ei[NE + e];
    atomicAdd(&g_wsum[d], ew[e]);
    atomicAdd(&g_degc[d], 1);
}

__global__ void __launch_bounds__(256) k_loopw() {
    int i = blockIdx.x * 256 + threadIdx.x;
    if (i < NN) {
        float deg = (float)(g_degc[i] - 1);
        g_loopw[i] = g_wsum[i] / fmaxf(deg, 1.0f);
    }
}

// ---------------- exclusive scan of g_degc -> g_rowp ------------------------
__global__ void __launch_bounds__(256) k_scan1() {
    __shared__ int sm[256];
    int t = threadIdx.x;
    int i = blockIdx.x * 256 + t;
    int v = (i < NN) ? g_degc[i] : 0;
    sm[t] = v;
    __syncthreads();
#pragma unroll
    for (int off = 1; off < 256; off <<= 1) {
        int x = (t >= off) ? sm[t - off] : 0;
        __syncthreads();
        sm[t] += x;
        __syncthreads();
    }
    if (i < NN) g_rowp[i] = sm[t] - v;
    if (t == 255) g_blksum[blockIdx.x] = sm[t];
}

__global__ void __launch_bounds__(256) k_scan2() {
    __shared__ int sm[256];
    int t = threadIdx.x;
    int v = (t < NBLK) ? g_blksum[t] : 0;
    sm[t] = v;
    __syncthreads();
#pragma unroll
    for (int off = 1; off < 256; off <<= 1) {
        int x = (t >= off) ? sm[t - off] : 0;
        __syncthreads();
        sm[t] += x;
        __syncthreads();
    }
    g_blkoff[t] = sm[t] - v;
}

__global__ void __launch_bounds__(256) k_scan3() {
    int i = blockIdx.x * 256 + threadIdx.x;
    if (i < NN) {
        int r = g_rowp[i] + g_blkoff[blockIdx.x];
        g_rowp[i] = r;
        g_fill[i] = r;
    }
    if (i == 0) g_rowp[NN] = NE2;
}

__global__ void __launch_bounds__(256) k_fill(const int* __restrict__ ei,
                                              const float* __restrict__ ew) {
    int e = blockIdx.x * 256 + threadIdx.x;
    if (e >= NE2) return;
    if (e < NE) {
        int s = ei[e], d = ei[NE + e];
        int pos = atomicAdd(&g_fill[d], 1);
        g_csrc[pos] = s;
        g_cw[pos] = ew[e];
    } else {
        int i = e - NE;
        int pos = atomicAdd(&g_fill[i], 1);
        g_csrc[pos] = i;
        g_cw[pos] = g_loopw[i];
    }
}

// ---------------- W -> W^T bf16 hi/lo images --------------------------------
__global__ void __launch_bounds__(256) k_conv_w(const float* __restrict__ Wl1,
                                                const float* __restrict__ Wr1,
                                                const float* __restrict__ Wl2,
                                                const float* __restrict__ Wr2) {
    int i = blockIdx.x * 256 + threadIdx.x;      // [0, 65536)
    int layer = i >> 15;
    int half  = (i >> 14) & 1;
    int e = i & 16383;
    int n = e >> 7, k = e & 127;
    const float* W = layer ? (half ? Wr2 : Wl2) : (half ? Wr1 : Wl1);
    float v = W[k * 128 + n];
    __nv_bfloat16 hi = __float2bfloat16_rn(v);
    __nv_bfloat16 lo = __float2bfloat16_rn(v - __bfloat162float(hi));
    g_Wbf[layer][half][0][e] = hi;
    g_Wbf[layer][half][1][e] = lo;
}

// ---------------- HMMA GEMM (R12 exact): C[M,128] = A @ W + bias ------------
// 3-term bf16 split: C = Ah@Bh + Al@Bh + Ah@Bl.
// blockIdx.y: 0 -> g_xl (Wl, bl), 1 -> g_xr (Wr, br). asel: 0 ext A, 1 g_h1.
// smem (bf16, pitch 136): Ah | Al | Bh | Bl, 34816 B each = 139264 B total.
#define HPITCH 136
#define HAS_B  34816
#define HG_SMEM (4 * 34816)

__global__ void __launch_bounds__(256) k_hgemm(const float* __restrict__ Aext,
                                               int asel, int layer,
                                               const float* __restrict__ bl,
                                               const float* __restrict__ br,
                                               int M) {
    extern __shared__ char smc[];
    const float* A    = asel ? (const float*)g_h1 : Aext;
    const int    y    = blockIdx.y;
    const float* bias = y ? br : bl;
    float*       gout = y ? (float*)g_xr : (float*)g_xl;

    const int tid = threadIdx.x;
    const int rowBase = blockIdx.x * 128;
    const uint32_t sb = smem_u32(smc);
    const uint32_t AH = sb, AL = sb + HAS_B, BH = sb + 2 * HAS_B, BL = sb + 3 * HAS_B;

    // ---- stage A: fp32 -> bf16 hi/lo into padded smem ----
    {
        int row = tid >> 1;
        int cb = (tid & 1) * 64;
        int gr = rowBase + row;
        if (gr >= M) gr = M - 1;
        const float4* src = (const float4*)(A + gr * 128 + cb);
        char* ah = smc + (row * HPITCH + cb) * 2;
        char* al = ah + HAS_B;
#pragma unroll
        for (int j = 0; j < 16; j++) {
            float4 v = src[j];
            __nv_bfloat16 hx = __float2bfloat16_rn(v.x);
            __nv_bfloat16 hy = __float2bfloat16_rn(v.y);
            __nv_bfloat16 hz = __float2bfloat16_rn(v.z);
            __nv_bfloat16 hw = __float2bfloat16_rn(v.w);
            uint2 h2 = make_uint2(pack2(hx, hy), pack2(hz, hw));
            uint2 l2 = make_uint2(
                pack2(__float2bfloat16_rn(v.x - __bfloat162float(hx)),
                      __float2bfloat16_rn(v.y - __bfloat162float(hy))),
                pack2(__float2bfloat16_rn(v.z - __bfloat162float(hz)),
                      __float2bfloat16_rn(v.w - __bfloat162float(hw))));
            *(uint2*)(ah + j * 8) = h2;
            *(uint2*)(al + j * 8) = l2;
        }
    }
    // ---- stage B: preconverted W^T bf16 -> padded smem ----
    {
        int n = tid >> 1;
        int kb = (tid & 1) * 64;
        const uint4* bh = (const uint4*)&g_Wbf[layer][y][0][n * 128 + kb];
        const uint4* blo = (const uint4*)&g_Wbf[layer][y][1][n * 128 + kb];
        char* dh = smc + 2 * HAS_B + (n * HPITCH + kb) * 2;
        char* dl = dh + HAS_B;
#pragma unroll
        for (int j = 0; j < 8; j++) {
            *(uint4*)(dh + j * 16) = bh[j];
            *(uint4*)(dl + j * 16) = blo[j];
        }
    }
    __syncthreads();

    // ---- compute: 8 warps, warp tile 32x64 ----
    const int lane = tid & 31, wid = tid >> 5;
    const int mrow = (wid & 3) * 32;
    const int ncol = (wid >> 2) * 64;
    const int q = lane >> 3, r = lane & 7;

    float acc[2][8][4];
#pragma unroll
    for (int a = 0; a < 2; a++)
#pragma unroll
        for (int b = 0; b < 8; b++)
#pragma unroll
            for (int c = 0; c < 4; c++) acc[a][b][c] = 0.f;

    const int bn = lane & 7, bq = (lane >> 3) & 1;

#pragma unroll
    for (int ks = 0; ks < 8; ks++) {
        int k0 = ks * 16;
        uint32_t ah[2][4], al[2][4];
#pragma unroll
        for (int mf = 0; mf < 2; mf++) {
            int arow = mrow + mf * 16 + (q & 1) * 8 + r;
            int akof = k0 + (q >> 1) * 8;
            uint32_t off = (uint32_t)(arow * HPITCH + akof) * 2;
            LDSM_X4(ah[mf][0], ah[mf][1], ah[mf][2], ah[mf][3], AH + off);
            LDSM_X4(al[mf][0], al[mf][1], al[mf][2], al[mf][3], AL + off);
        }
#pragma unroll
        for (int nf = 0; nf < 8; nf++) {
            int nrow = ncol + nf * 8 + bn;
            uint32_t boff = (uint32_t)(nrow * HPITCH + k0 + bq * 8) * 2;
            uint32_t bh0, bh1, bl0, bl1;
            LDSM_X2(bh0, bh1, BH + boff);
            LDSM_X2(bl0, bl1, BL + boff);
#pragma unroll
            for (int mf = 0; mf < 2; mf++) {
                MMA_BF16(acc[mf][nf], ah[mf], bh0, bh1);
                MMA_BF16(acc[mf][nf], al[mf], bh0, bh1);
                MMA_BF16(acc[mf][nf], ah[mf], bl0, bl1);
            }
        }
    }

    // ---- writeback + bias ----
#pragma unroll
    for (int mf = 0; mf < 2; mf++) {
        int row0 = rowBase + mrow + mf * 16 + (lane >> 2);
#pragma unroll
        for (int nf = 0; nf < 8; nf++) {
            int col = ncol + nf * 8 + (lane & 3) * 2;
            float b0 = bias[col], b1 = bias[col + 1];
            if (row0 < M) {
                float2 o = make_float2(acc[mf][nf][0] + b0, acc[mf][nf][1] + b1);
                *(float2*)(gout + row0 * 128 + col) = o;
            }
            if (row0 + 8 < M) {
                float2 o = make_float2(acc[mf][nf][2] + b0, acc[mf][nf][3] + b1);
                *(float2*)(gout + (row0 + 8) * 128 + col) = o;
            }
        }
    }
}

// ---------------- fused GATv2 attention (R12 exact): TWO warps per node -----
// mode 0: write agg. mode 1: write out = (emb + h1 + agg + bias2) / 3.
__global__ void __launch_bounds__(256) k_gat(const float* __restrict__ We,
                                             const float* __restrict__ att,
                                             int mode,
                                             const float* __restrict__ emb,
                                             const float* __restrict__ bias2,
                                             float* __restrict__ out) {
    __shared__ float4 s_acc[4][32];
    __shared__ float  s_den[4][32];

    int wid  = threadIdx.x >> 5;
    int slot = wid >> 1;
    int half = wid & 1;
    int lane = threadIdx.x & 31;
    int node = blockIdx.x * 4 + slot;
    if (node >= NN) return;

    float4 b  = g_xr[node * 32 + lane];
    float4 e4 = ((const float4*)We)[lane];
    float4 t4 = ((const float4*)att)[lane];

    int beg = g_rowp[node];
    int end = g_rowp[node + 1];

    float4 acc = make_float4(0.f, 0.f, 0.f, 0.f);
    float denom = 0.f;

    int j = beg + half;
    float w0 = 0.f, w1 = 0.f;
    float4 a0, a1;
    if (j < end)     { int s = g_csrc[j];     w0 = g_cw[j];     a0 = g_xl[s * 32 + lane]; }
    if (j + 2 < end) { int s = g_csrc[j + 2]; w1 = g_cw[j + 2]; a1 = g_xl[s * 32 + lane]; }

    for (; j < end; j += 2) {
        float w2 = 0.f; float4 a2;
        if (j + 4 < end) {
            int s2 = g_csrc[j + 4];
            w2 = g_cw[j + 4];
            a2 = g_xl[s2 * 32 + lane];
        }

        float mx = fmaf(w0, e4.x, a0.x + b.x); mx = fmaxf(mx, 0.2f * mx);
        float my = fmaf(w0, e4.y, a0.y + b.y); my = fmaxf(my, 0.2f * my);
        float mz = fmaf(w0, e4.z, a0.z + b.z); mz = fmaxf(mz, 0.2f * mz);
        float mw = fmaf(w0, e4.w, a0.w + b.w); mw = fmaxf(mw, 0.2f * mw);

        float p = mx * t4.x + my * t4.y + mz * t4.z + mw * t4.w;
        p += __shfl_xor_sync(0xffffffffu, p, 4);
        p += __shfl_xor_sync(0xffffffffu, p, 2);
        p += __shfl_xor_sync(0xffffffffu, p, 1);
        // logits tiny (weights scaled 0.05): unshifted exp == shifted softmax
        float e = __expf(p);
        denom += e;
        acc.x = fmaf(e, a0.x, acc.x);
        acc.y = fmaf(e, a0.y, acc.y);
        acc.z = fmaf(e, a0.z, acc.z);
        acc.w = fmaf(e, a0.w, acc.w);

        a0 = a1; w0 = w1;
        a1 = a2; w1 = w2;
    }

    if (half == 1) {
        s_acc[slot][lane] = acc;
        s_den[slot][lane] = denom;
    }
    __syncthreads();
    if (half == 1) return;

    float4 pa = s_acc[slot][lane];
    acc.x += pa.x; acc.y += pa.y; acc.z += pa.z; acc.w += pa.w;
    denom += s_den[slot][lane];

    float inv = __frcp_rn(denom);
    acc.x *= inv; acc.y *= inv; acc.z *= inv; acc.w *= inv;

    if (mode == 0) {
        g_agg[node * 32 + lane] = acc;
    } else {
        int i = node * 32 + lane;
        float4 e = ((const float4*)emb)[i];
        float4 h = g_h1[i];
        float4 bb = ((const float4*)bias2)[lane];
        float4 o;
        const float third = 1.0f / 3.0f;
        o.x = (e.x + h.x + acc.x + bb.x) * third;
        o.y = (e.y + h.y + acc.y + bb.y) * third;
        o.z = (e.z + h.z + acc.z + bb.z) * third;
        o.w = (e.w + h.w + acc.w + bb.w) * third;
        ((float4*)out)[i] = o;
    }
}

// ---------------- batchnorm -------------------------------------------------
__global__ void __launch_bounds__(256) k_bnstats() {
    int t = threadIdx.x;
    int f4 = t & 31;
    float4 s = make_float4(0.f, 0.f, 0.f, 0.f);
    float4 q = make_float4(0.f, 0.f, 0.f, 0.f);
    for (int r = blockIdx.x * 8 + (t >> 5); r < NN; r += gridDim.x * 8) {
        float4 v = g_agg[r * 32 + f4];
        s.x += v.x; s.y += v.y; s.z += v.z; s.w += v.w;
        q.x += v.x * v.x; q.y += v.y * v.y; q.z += v.z * v.z; q.w += v.w * v.w;
    }
    int j = f4 * 4;
    atomicAdd(&g_bnsum[j + 0], s.x); atomicAdd(&g_bnsum[j + 1], s.y);
    atomicAdd(&g_bnsum[j + 2], s.z); atomicAdd(&g_bnsum[j + 3], s.w);
    atomicAdd(&g_bnsq[j + 0], q.x);  atomicAdd(&g_bnsq[j + 1], q.y);
    atomicAdd(&g_bnsq[j + 2], q.z);  atomicAdd(&g_bnsq[j + 3], q.w);
}

__global__ void __launch_bounds__(128) k_bnfin(const float* __restrict__ gamma,
                                               const float* __restrict__ beta) {
    int j = threadIdx.x;
    float mean = g_bnsum[j] * (1.0f / NN);
    float var  = g_bnsq[j] * (1.0f / NN) - mean * mean;
    float inv  = rsqrtf(var + 1e-5f);
    float sc   = gamma[j] * inv;
    ((float*)g_bnscale)[j] = sc;
    ((float*)g_bnshift)[j] = beta[j] - mean * sc;
}

__global__ void __launch_bounds__(256) k_bnapply() {
    int i = blockIdx.x * 256 + threadIdx.x;
    if (i >= NN * 32) return;
    int f4 = i & 31;
    float4 v  = g_agg[i];
    float4 sc = g_bnscale[f4];
    float4 sh = g_bnshift[f4];
    float x;
    x = fmaf(v.x, sc.x, sh.x); v.x = x > 0.f ? x : expm1f(x);
    x = fmaf(v.y, sc.y, sh.y); v.y = x > 0.f ? x : expm1f(x);
    x = fmaf(v.z, sc.z, sh.z); v.z = x > 0.f ? x : expm1f(x);
    x = fmaf(v.w, sc.w, sh.w); v.w = x > 0.f ? x : expm1f(x);
    g_h1[i] = v;
}

// ---------------- launch ----------------------------------------------------
extern "C" void kernel_launch(void* const* d_in, const int* in_sizes, int n_in,
                              void* d_out, int out_size) {
    const float* emb   = (const float*)d_in[0];
    const int*   ei    = (const int*)d_in[1];      // int32
    const float* ew    = (const float*)d_in[2];
    const float* Wl1   = (const float*)d_in[3];
    const float* bl1   = (const float*)d_in[4];
    const float* Wr1   = (const float*)d_in[5];
    const float* br1   = (const float*)d_in[6];
    const float* We1   = (const float*)d_in[7];
    const float* att1  = (const float*)d_in[8];
    // d_in[9] = bias1 : cancels exactly inside BatchNorm, unused
    const float* gamma1 = (const float*)d_in[10];
    const float* beta1  = (const float*)d_in[11];
    const float* Wl2   = (const float*)d_in[12];
    const float* bl2   = (const float*)d_in[13];
    const float* Wr2   = (const float*)d_in[14];
    const float* br2   = (const float*)d_in[15];
    const float* We2   = (const float*)d_in[16];
    const float* att2  = (const float*)d_in[17];
    const float* bias2 = (const float*)d_in[18];
    float* out = (float*)d_out;

    static cudaStream_t sB = nullptr;
    static cudaEvent_t  eF = nullptr, eJ = nullptr;
    static int smem_set = 0;
    if (!smem_set) {
        cudaFuncSetAttribute(k_hgemm, cudaFuncAttributeMaxDynamicSharedMemorySize,
                             HG_SMEM);
        cudaStreamCreateWithFlags(&sB, cudaStreamNonBlocking);
        cudaEventCreateWithFlags(&eF, cudaEventDisableTiming);
        cudaEventCreateWithFlags(&eJ, cudaEventDisableTiming);
        smem_set = 1;
    }

    const int NB_N  = NBLK;
    const int NB_E  = (NE + 255) / 256;
    const int NB_E2 = (NE2 + 255) / 256;
    const int NB_G  = (NN + 3) / 4;
    const int NB_F  = (NN * 32 + 255) / 256;
    dim3 gemm_grid((NN + 127) / 128, 2);

    // ---- fork: CSR build chain on sB, concurrent with conv_w + hgemm1 ----
    cudaEventRecord(eF, 0);
    cudaStreamWaitEvent(sB, eF, 0);

    k_zero_pre<<<NB_N, 256, 0, sB>>>();
    k_selfloop<<<NB_E, 256, 0, sB>>>(ei, ew);
    k_loopw<<<NB_N, 256, 0, sB>>>();
    k_scan1<<<NBLK, 256, 0, sB>>>();
    k_scan2<<<1, 256, 0, sB>>>();
    k_scan3<<<NBLK, 256, 0, sB>>>();
    k_fill<<<NB_E2, 256, 0, sB>>>(ei, ew);
    cudaEventRecord(eJ, sB);

    // main stream: W images + layer-1 dual GEMM (independent of CSR)
    k_conv_w<<<256, 256>>>(Wl1, Wr1, Wl2, Wr2);
    k_hgemm<<<gemm_grid, 256, HG_SMEM>>>(emb, 0, 0, bl1, br1, NN);

    // join: gat needs both CSR and GEMM outputs
    cudaStreamWaitEvent(0, eJ, 0);

    // ---- layer 1 attention + BN ----
    k_gat<<<NB_G, 256>>>(We1, att1, 0, emb, bias2, out);
    k_bnstats<<<512, 256>>>();
    k_bnfin<<<1, 128>>>(gamma1, beta1);
    k_bnapply<<<NB_F, 256>>>();

    // ---- layer 2 ----
    k_hgemm<<<gemm_grid, 256, HG_SMEM>>>(emb, 1, 1, bl2, br2, NN);
    // fused final: out = (emb + h1 + (agg + bias2)) / 3
    k_gat<<<NB_G, 256>>>(We2, att2, 1, emb, bias2, out);
}